// round 16
// baseline (speedup 1.0000x reference)
#include <cuda_runtime.h>
#include <cuda_fp16.h>

#define NN 50000
#define EE 800000
#define FH 128
#define SCAN_B 256
#define NBLK ((NN + SCAN_B - 1) / SCAN_B)
#define EPW 8   // edges per warp in k_edge

// ---------------- scratch (device globals; no allocation allowed) ----------------
__device__ int      g_is64;
__device__ int      g_total;                  // CSR base allocator (reset by prolog)
__device__ int      g_degi[NN];
__device__ int      g_ptr[NN];
__device__ int2     g_e2[EE];                 // CSR slot: {src | dst<<16, eid}
__device__ __half   g_xh[(size_t)NN * 128];   // x in fp16
__device__ __half   g_cath[(size_t)NN * 256]; // [agg | root] fp16, GEMM input
__device__ __half   g_h1h[(size_t)NN * 128];
__device__ __half   g_h2h[(size_t)NN * 128];
__device__ __half   g_ABh[(size_t)NN * 512];  // cols 0..255 = A(+b3), 256..511 = B
__device__ __half   g_WhA[3][512 * 128];      // packed weights per stage, n-major [N][K]
__device__ float    g_biasA[3][512];
__device__ int      g_pair[EE];               // decoded s|d<<16 (written by k_count)
__device__ int      g_rank[EE];               // edge's rank within its dst segment

// ================= prolog A: init degrees + dtype detect (stream 0, feeds CSR chain) =================
__global__ void k_prolog(const int* __restrict__ ei_raw) {
    int i = blockIdx.x * blockDim.x + threadIdx.x;
    if (i < NN) g_degi[i] = 0;
    if (blockIdx.x == 0) {
        if (threadIdx.x == 0) g_total = 0;
        __shared__ int nz;
        if (threadIdx.x == 0) nz = 0;
        __syncthreads();
        for (int j = threadIdx.x; j < 1024; j += 256)
            if (ei_raw[2 * j + 1] != 0) nz = 1;
        __syncthreads();
        if (threadIdx.x == 0) g_is64 = (nz == 0) ? 1 : 0;
    }
}

// ================= prolog B: weight packs + x->fp16 (side stream, overlaps CSR build) =================
// block ranges: [0,Q1) packW1 | [Q1,Q2) packW2 | [Q2,Q3) packW3 | [Q3,Q4) x->half
#define Q1 128
#define Q2 (Q1 + 128)
#define Q3 (Q2 + 256)
#define Q4 (Q3 + (NN * 128 / 8 + 255) / 256)

__global__ void k_packx(const float* __restrict__ X,
                        const float* __restrict__ W1l, const float* __restrict__ W1r,
                        const float* __restrict__ b1l,
                        const float* __restrict__ W2l, const float* __restrict__ W2r,
                        const float* __restrict__ b2l,
                        const float* __restrict__ W3,  const float* __restrict__ b3) {
    int b = blockIdx.x, t = threadIdx.x;
    if (b < Q2) {
        int stage = (b < Q1) ? 0 : 1;
        const float* Wl = stage ? W2l : W1l;
        const float* Wr = stage ? W2r : W1r;
        const float* bb = stage ? b2l : b1l;
        int i = (b - (stage ? Q1 : 0)) * 256 + t;     // over 128*256
        if (i < 128) g_biasA[stage][i] = bb[i];
        int n = i >> 8, k = i & 255;
        float v = (k < 128) ? Wl[k * 128 + n] : Wr[(k - 128) * 128 + n];
        g_WhA[stage][n * 256 + k] = __float2half_rn(v);
    } else if (b < Q3) {
        int i = (b - Q2) * 256 + t;                   // over 512*128
        if (i < 512) g_biasA[2][i] = (i < 256) ? b3[i] : 0.f;
        int n = i >> 7, k = i & 127;
        float v = (n < 256) ? W3[k * 256 + n] : W3[(128 + k) * 256 + (n - 256)];
        g_WhA[2][n * 128 + k] = __float2half_rn(v);
    } else {
        size_t i = (size_t)((b - Q3) * 256 + t) * 8;
        if (i >= (size_t)NN * 128) return;
        float4 a = *(const float4*)(X + i);
        float4 c = *(const float4*)(X + i + 4);
        __half2 h0 = __floats2half2_rn(a.x, a.y), h1 = __floats2half2_rn(a.z, a.w);
        __half2 h2 = __floats2half2_rn(c.x, c.y), h3 = __floats2half2_rn(c.z, c.w);
        uint4 o;
        o.x = *(unsigned*)&h0; o.y = *(unsigned*)&h1; o.z = *(unsigned*)&h2; o.w = *(unsigned*)&h3;
        *(uint4*)(g_xh + i) = o;
    }
}

// ---------------- CSR construction ----------------
__global__ void k_count(const int* __restrict__ ei) {
    int e = blockIdx.x * blockDim.x + threadIdx.x;
    if (e >= EE) return;
    int s, d;
    if (g_is64) { s = ei[2 * (size_t)e]; d = ei[2 * ((size_t)EE + e)]; }
    else        { s = ei[e];             d = ei[(size_t)EE + e]; }
    if ((unsigned)s >= NN) s = 0;
    if ((unsigned)d >= NN) d = 0;
    g_pair[e] = s | (d << 16);
    g_rank[e] = atomicAdd(&g_degi[d], 1);
}

__global__ void k_ptr() {
    int b = blockIdx.x, t = threadIdx.x, i = b * SCAN_B + t;
    int lane = t & 31, w = t >> 5;
    int v = (i < NN) ? g_degi[i] : 0;
    int sc = v;
    #pragma unroll
    for (int o = 1; o < 32; o <<= 1) { int x = __shfl_up_sync(0xffffffffu, sc, o); if (lane >= o) sc += x; }
    __shared__ int ws[8];
    if (lane == 31) ws[w] = sc;
    __syncthreads();
    int add = 0, tot = 0;
    #pragma unroll
    for (int j = 0; j < 8; j++) { if (j < w) add += ws[j]; tot += ws[j]; }
    __shared__ int base;
    if (t == 0) base = atomicAdd(&g_total, tot);
    __syncthreads();
    if (i < NN) g_ptr[i] = base + add + sc - v;
}

__global__ void k_fill() {
    int e = blockIdx.x * blockDim.x + threadIdx.x;
    if (e >= EE) return;
    int pr = g_pair[e];
    int d = (int)(((unsigned)pr) >> 16);
    g_e2[g_ptr[d] + g_rank[e]] = make_int2(pr, e);
}

// ---------------- mean aggregation: warp per node; indices via shuffle, 4-wide row loads ----------------
__global__ void k_agg(const __half* __restrict__ Xg, const __half* __restrict__ Xr) {
    int t = blockIdx.x * blockDim.x + threadIdx.x;
    int node = t >> 5, lane = t & 31;
    if (node >= NN) return;
    int beg = g_ptr[node];
    int deg = g_degi[node];
    float a0 = 0.f, a1 = 0.f, a2 = 0.f, a3 = 0.f;
    for (int j0 = 0; j0 < deg; j0 += 32) {
        int n = deg - j0; if (n > 32) n = 32;
        int idx = 0;
        if (lane < n) idx = g_e2[beg + j0 + lane].x & 0xffff;
        int j = 0;
        for (; j + 4 <= n; j += 4) {
            int s0 = __shfl_sync(0xffffffffu, idx, j);
            int s1 = __shfl_sync(0xffffffffu, idx, j + 1);
            int s2 = __shfl_sync(0xffffffffu, idx, j + 2);
            int s3 = __shfl_sync(0xffffffffu, idx, j + 3);
            uint2 v0 = ((const uint2*)(Xg + (size_t)s0 * FH))[lane];
            uint2 v1 = ((const uint2*)(Xg + (size_t)s1 * FH))[lane];
            uint2 v2 = ((const uint2*)(Xg + (size_t)s2 * FH))[lane];
            uint2 v3 = ((const uint2*)(Xg + (size_t)s3 * FH))[lane];
            float2 f;
            f = __half22float2(*(__half2*)&v0.x); a0 += f.x; a1 += f.y;
            f = __half22float2(*(__half2*)&v0.y); a2 += f.x; a3 += f.y;
            f = __half22float2(*(__half2*)&v1.x); a0 += f.x; a1 += f.y;
            f = __half22float2(*(__half2*)&v1.y); a2 += f.x; a3 += f.y;
            f = __half22float2(*(__half2*)&v2.x); a0 += f.x; a1 += f.y;
            f = __half22float2(*(__half2*)&v2.y); a2 += f.x; a3 += f.y;
            f = __half22float2(*(__half2*)&v3.x); a0 += f.x; a1 += f.y;
            f = __half22float2(*(__half2*)&v3.y); a2 += f.x; a3 += f.y;
        }
        for (; j < n; j++) {
            int s = __shfl_sync(0xffffffffu, idx, j);
            uint2 v = ((const uint2*)(Xg + (size_t)s * FH))[lane];
            float2 f;
            f = __half22float2(*(__half2*)&v.x); a0 += f.x; a1 += f.y;
            f = __half22float2(*(__half2*)&v.y); a2 += f.x; a3 += f.y;
        }
    }
    float inv = 1.0f / (float)(deg > 1 ? deg : 1);
    __half2 o0 = __floats2half2_rn(a0 * inv, a1 * inv);
    __half2 o1 = __floats2half2_rn(a2 * inv, a3 * inv);
    uint2 pack; pack.x = *(unsigned*)&o0; pack.y = *(unsigned*)&o1;
    ((uint2*)(g_cath + (size_t)node * 256))[lane] = pack;                       // agg half
    ((uint2*)(g_cath + (size_t)node * 256 + 128))[lane] =
        ((const uint2*)(Xr + (size_t)node * FH))[lane];                         // root half
}

// ---------------- cp.async helper ----------------
__device__ __forceinline__ void cp16(void* smem, const void* gmem, bool pred) {
    unsigned saddr = (unsigned)__cvta_generic_to_shared(smem);
    int sz = pred ? 16 : 0;   // src_size=0 -> zero-fill 16B, no gmem access
    asm volatile("cp.async.cg.shared.global [%0], [%1], 16, %2;\n"
                 :: "r"(saddr), "l"(gmem), "r"(sz));
}

// ---------------- fp16 tensor-core GEMM, 3-stage cp.async pipeline (FROZEN config) ----------------
// tile 128x128, BK=32; 8 warps of 32x64 m16n8k16. (256,3) and 64x128 both measured slower.
template<bool RELU>
__global__ __launch_bounds__(256) void gemm_h(const __half* __restrict__ A, int M, int K,
                                              const __half* __restrict__ Wp,
                                              const float* __restrict__ bias,
                                              __half* __restrict__ C, int ldc) {
    __shared__ __align__(16) __half As[3][128][40];
    __shared__ __align__(16) __half Bs[3][128][40];
    const int tid = threadIdx.x;
    const int bm = blockIdx.y * 128;
    const int bn = blockIdx.x * 128;
    const int wid = tid >> 5, lane = tid & 31;
    const int warp_m = (wid & 3) * 32, warp_n = (wid >> 2) * 64;
    const int g = lane >> 2, q = lane & 3;
    const int KT = K >> 5;

    float acc[2][8][4];
    #pragma unroll
    for (int i = 0; i < 2; i++)
        #pragma unroll
        for (int j = 0; j < 8; j++)
            #pragma unroll
            for (int r = 0; r < 4; r++) acc[i][j][r] = 0.f;

    const int r0c = tid >> 2,         c0c = (tid & 3) * 8;
    const int r1c = (tid + 256) >> 2, c1c = ((tid + 256) & 3) * 8;
    auto load_stage = [&](int buf, int k0) {
        bool p0 = (bm + r0c) < M, p1 = (bm + r1c) < M;
        cp16(&As[buf][r0c][c0c], A + (size_t)(bm + (p0 ? r0c : 0)) * K + k0 + c0c, p0);
        cp16(&As[buf][r1c][c1c], A + (size_t)(bm + (p1 ? r1c : 0)) * K + k0 + c1c, p1);
        cp16(&Bs[buf][r0c][c0c], Wp + (size_t)(bn + r0c) * K + k0 + c0c, true);
        cp16(&Bs[buf][r1c][c1c], Wp + (size_t)(bn + r1c) * K + k0 + c1c, true);
        asm volatile("cp.async.commit_group;\n");
    };

    load_stage(0, 0);
    if (KT > 1) load_stage(1, 32); else asm volatile("cp.async.commit_group;\n");
    for (int kt = 0; kt < KT; kt++) {
        asm volatile("cp.async.wait_group 1;\n");
        __syncthreads();
        if (kt + 2 < KT) load_stage((kt + 2) % 3, (kt + 2) << 5);
        else asm volatile("cp.async.commit_group;\n");
        const int buf = kt % 3;
        #pragma unroll
        for (int ks = 0; ks < 32; ks += 16) {
            unsigned a[2][4], b[8][2];
            #pragma unroll
            for (int mt = 0; mt < 2; mt++) {
                int rr = warp_m + mt * 16 + g;
                a[mt][0] = *(const unsigned*)&As[buf][rr][ks + 2 * q];
                a[mt][1] = *(const unsigned*)&As[buf][rr + 8][ks + 2 * q];
                a[mt][2] = *(const unsigned*)&As[buf][rr][ks + 2 * q + 8];
                a[mt][3] = *(const unsigned*)&As[buf][rr + 8][ks + 2 * q + 8];
            }
            #pragma unroll
            for (int nt = 0; nt < 8; nt++) {
                int c = warp_n + nt * 8 + g;
                b[nt][0] = *(const unsigned*)&Bs[buf][c][ks + 2 * q];
                b[nt][1] = *(const unsigned*)&Bs[buf][c][ks + 2 * q + 8];
            }
            #pragma unroll
            for (int mt = 0; mt < 2; mt++)
                #pragma unroll
                for (int nt = 0; nt < 8; nt++) {
                    float* cr = acc[mt][nt];
                    asm volatile(
                        "mma.sync.aligned.m16n8k16.row.col.f32.f16.f16.f32 "
                        "{%0,%1,%2,%3}, {%4,%5,%6,%7}, {%8,%9}, {%0,%1,%2,%3};\n"
                        : "+f"(cr[0]), "+f"(cr[1]), "+f"(cr[2]), "+f"(cr[3])
                        : "r"(a[mt][0]), "r"(a[mt][1]), "r"(a[mt][2]), "r"(a[mt][3]),
                          "r"(b[nt][0]), "r"(b[nt][1]));
                }
        }
    }
    #pragma unroll
    for (int mt = 0; mt < 2; mt++) {
        int r0 = bm + warp_m + mt * 16 + g;
        #pragma unroll
        for (int nt = 0; nt < 8; nt++) {
            int c0 = bn + warp_n + nt * 8 + 2 * q;
            float bi0 = bias[c0], bi1 = bias[c0 + 1];
            if (r0 < M) {
                float v0 = acc[mt][nt][0] + bi0, v1 = acc[mt][nt][1] + bi1;
                if (RELU) { v0 = fmaxf(v0, 0.f); v1 = fmaxf(v1, 0.f); }
                *(__half2*)(C + (size_t)r0 * ldc + c0) = __floats2half2_rn(v0, v1);
            }
            if (r0 + 8 < M) {
                float v2 = acc[mt][nt][2] + bi0, v3 = acc[mt][nt][3] + bi1;
                if (RELU) { v2 = fmaxf(v2, 0.f); v3 = fmaxf(v3, 0.f); }
                *(__half2*)(C + (size_t)(r0 + 8) * ldc + c0) = __floats2half2_rn(v2, v3);
            }
        }
    }
}

// ---------------- per-edge prediction: warp handles EPW edges, W4 in regs ----------------
__global__ void k_edge(const float* __restrict__ W4, const float* __restrict__ b4,
                       float* __restrict__ out) {
    int tid = threadIdx.x, lane = tid & 31;
    int warp = (blockIdx.x * blockDim.x + tid) >> 5;
    float4 w0 = ((const float4*)W4)[lane * 2];
    float4 w1 = ((const float4*)W4)[lane * 2 + 1];
    float bb = b4[0];
    const __half2 hz = __floats2half2_rn(0.f, 0.f);
    int base = warp * EPW;
    #pragma unroll
    for (int i = 0; i < EPW; i++) {
        int p = base + i;
        if (p >= EE) return;
        int2 v = g_e2[p];
        int s = v.x & 0xffff;
        int d = (int)(((unsigned)v.x) >> 16);
        const uint4* Ar = (const uint4*)(g_ABh + (size_t)s * 512);
        const uint4* Br = (const uint4*)(g_ABh + (size_t)d * 512 + 256);
        uint4 a = Ar[lane];
        uint4 b = Br[lane];
        __half2 t0 = __hmax2(__hadd2(*(__half2*)&a.x, *(__half2*)&b.x), hz);
        __half2 t1 = __hmax2(__hadd2(*(__half2*)&a.y, *(__half2*)&b.y), hz);
        __half2 t2 = __hmax2(__hadd2(*(__half2*)&a.z, *(__half2*)&b.z), hz);
        __half2 t3 = __hmax2(__hadd2(*(__half2*)&a.w, *(__half2*)&b.w), hz);
        float2 f0 = __half22float2(t0), f1 = __half22float2(t1);
        float2 f2 = __half22float2(t2), f3 = __half22float2(t3);
        float acc = f0.x * w0.x + f0.y * w0.y + f1.x * w0.z + f1.y * w0.w +
                    f2.x * w1.x + f2.y * w1.y + f3.x * w1.z + f3.y * w1.w;
        #pragma unroll
        for (int o = 16; o; o >>= 1) acc += __shfl_down_sync(0xffffffffu, acc, o);
        if (lane == 0) out[v.y] = acc + bb;
    }
}

// ---------------- launch ----------------
extern "C" void kernel_launch(void* const* d_in, const int* in_sizes, int n_in,
                              void* d_out, int out_size) {
    const float* x   = (const float*)d_in[0];
    const int*   ei  = (const int*)d_in[1];   // dtype sniffed at runtime (int32 vs int64)
    const float* W1l = (const float*)d_in[2];
    const float* b1l = (const float*)d_in[3];
    const float* W1r = (const float*)d_in[4];
    const float* W2l = (const float*)d_in[5];
    const float* b2l = (const float*)d_in[6];
    const float* W2r = (const float*)d_in[7];
    const float* W3  = (const float*)d_in[8];
    const float* b3  = (const float*)d_in[9];
    const float* W4  = (const float*)d_in[10];
    const float* b4  = (const float*)d_in[11];
    float* out = (float*)d_out;

    __half *p_xh, *p_cath, *p_h1h, *p_h2h, *p_ABh, *p_Wh;
    float  *p_bias;
    cudaGetSymbolAddress((void**)&p_xh,   g_xh);
    cudaGetSymbolAddress((void**)&p_cath, g_cath);
    cudaGetSymbolAddress((void**)&p_h1h,  g_h1h);
    cudaGetSymbolAddress((void**)&p_h2h,  g_h2h);
    cudaGetSymbolAddress((void**)&p_ABh,  g_ABh);
    cudaGetSymbolAddress((void**)&p_Wh,   g_WhA);
    cudaGetSymbolAddress((void**)&p_bias, g_biasA);

    // one-time side stream + events (created outside capture on the correctness run,
    // reused inside graph capture — fork-join event pattern is capture-legal)
    static cudaStream_t s2 = nullptr;
    static cudaEvent_t evFork = nullptr, evJoin = nullptr;
    if (!s2) {
        cudaStreamCreateWithFlags(&s2, cudaStreamNonBlocking);
        cudaEventCreateWithFlags(&evFork, cudaEventDisableTiming);
        cudaEventCreateWithFlags(&evJoin, cudaEventDisableTiming);
    }

    const int TB = 256;
    // fork: side stream packs weights + converts x while stream 0 builds the CSR
    cudaEventRecord(evFork, 0);
    cudaStreamWaitEvent(s2, evFork, 0);
    k_packx<<<Q4, TB, 0, s2>>>(x, W1l, W1r, b1l, W2l, W2r, b2l, W3, b3);

    k_prolog<<<NBLK, TB>>>(ei);
    k_count<<<(EE + TB - 1) / TB, TB>>>(ei);
    k_ptr<<<NBLK, SCAN_B>>>();
    k_fill<<<(EE + TB - 1) / TB, TB>>>();

    // join: agg1 needs g_xh (side stream) + CSR (stream 0)
    cudaEventRecord(evJoin, s2);
    cudaStreamWaitEvent(0, evJoin, 0);

    const int aggGrid = (NN * 32 + TB - 1) / TB;
    const int mTiles  = (NN + 127) / 128;   // 391

    // SAGE layer 1: h1 = relu([mean_agg(x)|x] @ [W1l;W1r] + b1l)
    k_agg<<<aggGrid, TB>>>(p_xh, p_xh);
    gemm_h<true><<<dim3(1, mTiles), 256>>>(p_cath, NN, 256, p_Wh, p_bias, p_h1h, 128);

    // SAGE layer 2
    k_agg<<<aggGrid, TB>>>(p_h1h, p_h1h);
    gemm_h<true><<<dim3(1, mTiles), 256>>>(p_cath, NN, 256, p_Wh + 512 * 128, p_bias + 512, p_h2h, 128);

    // Edge-MLP factorization: ABh[:,0:256] = h2@W3_top + b3, ABh[:,256:512] = h2@W3_bot
    gemm_h<false><<<dim3(4, mTiles), 256>>>(p_h2h, NN, 128, p_Wh + 2 * 512 * 128, p_bias + 2 * 512, p_ABh, 512);

    // Per-edge: dot(relu(A[src]+B[dst]), W4) + b4 (dst-grouped CSR order, EPW edges/warp)
    const int edgeWarps = (EE + EPW - 1) / EPW;
    k_edge<<<(edgeWarps * 32 + TB - 1) / TB, TB>>>(W4, b4, out);
}

// round 17
// speedup vs baseline: 1.0229x; 1.0229x over previous
#include <cuda_runtime.h>
#include <cuda_fp16.h>

#define NN 50000
#define EE 800000
#define FH 128
#define SCAN_B 256
#define NBLK ((NN + SCAN_B - 1) / SCAN_B)
#define EPW 8   // edges per warp in k_edge

// ---------------- scratch (device globals; no allocation allowed) ----------------
__device__ int      g_is64;
__device__ int      g_total;                  // CSR base allocator (reset by prolog)
__device__ int      g_degi[NN];
__device__ int      g_ptr[NN];
__device__ int2     g_e2[EE];                 // CSR slot: {src | dst<<16, eid}
__device__ __half   g_xh[(size_t)NN * 128];   // x in fp16
__device__ __half   g_aggh[(size_t)NN * 128]; // mean-aggregated features (fp16)
__device__ __half   g_h1h[(size_t)NN * 128];
__device__ __half   g_h2h[(size_t)NN * 128];
__device__ __half   g_ABh[(size_t)NN * 512];  // cols 0..255 = A(+b3), 256..511 = B
__device__ __half   g_WhA[3][512 * 128];      // packed weights per stage, n-major [N][K]
__device__ float    g_biasA[3][512];
__device__ int      g_pair[EE];               // decoded s|d<<16 (written by k_count)
__device__ int      g_rank[EE];               // edge's rank within its dst segment

// ================= K1: fused init + dtype detect + all weight packs + x->fp16 =================
// block ranges: [0,P0) init/detect | [P0,P1) packW1 | [P1,P2) packW2 | [P2,P3) packW3 | [P3,P4) half
#define P0 NBLK
#define P1 (P0 + 128)
#define P2 (P1 + 128)
#define P3 (P2 + 256)
#define P4 (P3 + (NN * 128 / 8 + 255) / 256)

__global__ void k_prolog(const int* __restrict__ ei_raw, const float* __restrict__ X,
                         const float* __restrict__ W1l, const float* __restrict__ W1r,
                         const float* __restrict__ b1l,
                         const float* __restrict__ W2l, const float* __restrict__ W2r,
                         const float* __restrict__ b2l,
                         const float* __restrict__ W3,  const float* __restrict__ b3) {
    int b = blockIdx.x, t = threadIdx.x;
    if (b < P0) {
        int i = b * 256 + t;
        if (i < NN) g_degi[i] = 0;
        if (b == 0) {
            if (t == 0) g_total = 0;
            __shared__ int nz;
            if (t == 0) nz = 0;
            __syncthreads();
            for (int j = t; j < 1024; j += 256)
                if (ei_raw[2 * j + 1] != 0) nz = 1;
            __syncthreads();
            if (t == 0) g_is64 = (nz == 0) ? 1 : 0;
        }
    } else if (b < P2) {
        int stage = (b < P1) ? 0 : 1;
        const float* Wl = stage ? W2l : W1l;
        const float* Wr = stage ? W2r : W1r;
        const float* bb = stage ? b2l : b1l;
        int i = (b - (stage ? P1 : P0)) * 256 + t;    // over 128*256
        if (i < 128) g_biasA[stage][i] = bb[i];
        int n = i >> 8, k = i & 255;
        float v = (k < 128) ? Wl[k * 128 + n] : Wr[(k - 128) * 128 + n];
        g_WhA[stage][n * 256 + k] = __float2half_rn(v);
    } else if (b < P3) {
        int i = (b - P2) * 256 + t;                   // over 512*128
        if (i < 512) g_biasA[2][i] = (i < 256) ? b3[i] : 0.f;
        int n = i >> 7, k = i & 127;
        float v = (n < 256) ? W3[k * 256 + n] : W3[(128 + k) * 256 + (n - 256)];
        g_WhA[2][n * 128 + k] = __float2half_rn(v);
    } else {
        size_t i = (size_t)((b - P3) * 256 + t) * 8;
        if (i >= (size_t)NN * 128) return;
        float4 a = *(const float4*)(X + i);
        float4 c = *(const float4*)(X + i + 4);
        __half2 h0 = __floats2half2_rn(a.x, a.y), h1 = __floats2half2_rn(a.z, a.w);
        __half2 h2 = __floats2half2_rn(c.x, c.y), h3 = __floats2half2_rn(c.z, c.w);
        uint4 o;
        o.x = *(unsigned*)&h0; o.y = *(unsigned*)&h1; o.z = *(unsigned*)&h2; o.w = *(unsigned*)&h3;
        *(uint4*)(g_xh + i) = o;
    }
}

// ---------------- CSR construction ----------------
// count: decode once; atomicAdd return value IS the edge's rank within its dst segment.
__global__ void k_count(const int* __restrict__ ei) {
    int e = blockIdx.x * blockDim.x + threadIdx.x;
    if (e >= EE) return;
    int s, d;
    if (g_is64) { s = ei[2 * (size_t)e]; d = ei[2 * ((size_t)EE + e)]; }
    else        { s = ei[e];             d = ei[(size_t)EE + e]; }
    if ((unsigned)s >= NN) s = 0;
    if ((unsigned)d >= NN) d = 0;
    g_pair[e] = s | (d << 16);
    g_rank[e] = atomicAdd(&g_degi[d], 1);
}

// one-shot segment-base assignment: block-local scan + single atomicAdd for the base.
__global__ void k_ptr() {
    int b = blockIdx.x, t = threadIdx.x, i = b * SCAN_B + t;
    int lane = t & 31, w = t >> 5;
    int v = (i < NN) ? g_degi[i] : 0;
    int sc = v;
    #pragma unroll
    for (int o = 1; o < 32; o <<= 1) { int x = __shfl_up_sync(0xffffffffu, sc, o); if (lane >= o) sc += x; }
    __shared__ int ws[8];
    if (lane == 31) ws[w] = sc;
    __syncthreads();
    int add = 0, tot = 0;
    #pragma unroll
    for (int j = 0; j < 8; j++) { if (j < w) add += ws[j]; tot += ws[j]; }
    __shared__ int base;
    if (t == 0) base = atomicAdd(&g_total, tot);
    __syncthreads();
    if (i < NN) g_ptr[i] = base + add + sc - v;
}

// fill: atomic-free — pos = ptr[d] + precomputed rank
__global__ void k_fill() {
    int e = blockIdx.x * blockDim.x + threadIdx.x;
    if (e >= EE) return;
    int pr = g_pair[e];
    int d = (int)(((unsigned)pr) >> 16);
    g_e2[g_ptr[d] + g_rank[e]] = make_int2(pr, e);
}

// ---------------- mean aggregation (fp16 in, fp32 acc, fp16 out): warp per node ----------------
// writes ONLY the aggregate (root half is read directly by the GEMM — no copy)
__global__ void k_agg(const __half* __restrict__ Xg) {
    int t = blockIdx.x * blockDim.x + threadIdx.x;
    int node = t >> 5, lane = t & 31;
    if (node >= NN) return;
    int beg = g_ptr[node];
    int deg = g_degi[node];
    float a0 = 0.f, a1 = 0.f, a2 = 0.f, a3 = 0.f;
    for (int j = 0; j < deg; j++) {
        int s = g_e2[beg + j].x & 0xffff;
        uint2 v = ((const uint2*)(Xg + (size_t)s * FH))[lane];   // 4 halves
        float2 f0 = __half22float2(*(__half2*)&v.x);
        float2 f1 = __half22float2(*(__half2*)&v.y);
        a0 += f0.x; a1 += f0.y; a2 += f1.x; a3 += f1.y;
    }
    float inv = 1.0f / (float)(deg > 1 ? deg : 1);
    __half2 o0 = __floats2half2_rn(a0 * inv, a1 * inv);
    __half2 o1 = __floats2half2_rn(a2 * inv, a3 * inv);
    uint2 pack; pack.x = *(unsigned*)&o0; pack.y = *(unsigned*)&o1;
    ((uint2*)(g_aggh + (size_t)node * 128))[lane] = pack;
}

// ---------------- cp.async helper ----------------
__device__ __forceinline__ void cp16(void* smem, const void* gmem, bool pred) {
    unsigned saddr = (unsigned)__cvta_generic_to_shared(smem);
    int sz = pred ? 16 : 0;   // src_size=0 -> zero-fill 16B, no gmem access
    asm volatile("cp.async.cg.shared.global [%0], [%1], 16, %2;\n"
                 :: "r"(saddr), "l"(gmem), "r"(sz));
}

// ---------------- fp16 tensor-core GEMM, 3-stage cp.async pipeline (FROZEN mainloop) ----------------
// C = op([A1|A2][M,K] @ Wp^T + bias), fp32 accum. tile 128x128, BK=32; 8 warps of 32x64 m16n8k16.
// A is split: k<128 rows come from A1 (lda=128), k>=128 from A2 (lda=128). K-tiles (32)
// never straddle the boundary, so the loader just picks a pointer per stage. For K=128
// pass A1==A2. (256,3) and 64x128 tile both measured slower — mainloop unchanged.
template<bool RELU>
__global__ __launch_bounds__(256) void gemm_h(const __half* __restrict__ A1,
                                              const __half* __restrict__ A2, int M, int K,
                                              const __half* __restrict__ Wp,
                                              const float* __restrict__ bias,
                                              __half* __restrict__ C, int ldc) {
    __shared__ __align__(16) __half As[3][128][40];
    __shared__ __align__(16) __half Bs[3][128][40];
    const int tid = threadIdx.x;
    const int bm = blockIdx.y * 128;
    const int bn = blockIdx.x * 128;
    const int wid = tid >> 5, lane = tid & 31;
    const int warp_m = (wid & 3) * 32, warp_n = (wid >> 2) * 64;
    const int g = lane >> 2, q = lane & 3;
    const int KT = K >> 5;

    float acc[2][8][4];
    #pragma unroll
    for (int i = 0; i < 2; i++)
        #pragma unroll
        for (int j = 0; j < 8; j++)
            #pragma unroll
            for (int r = 0; r < 4; r++) acc[i][j][r] = 0.f;

    // loader: 128 rows x 32 halves = 512 x 16B chunks per array; thread -> chunks {tid, tid+256}
    const int r0c = tid >> 2,         c0c = (tid & 3) * 8;
    const int r1c = (tid + 256) >> 2, c1c = ((tid + 256) & 3) * 8;
    auto load_stage = [&](int buf, int k0) {
        const __half* Asrc = (k0 < 128) ? A1 : A2;
        int kk = (k0 < 128) ? k0 : (k0 - 128);
        bool p0 = (bm + r0c) < M, p1 = (bm + r1c) < M;
        cp16(&As[buf][r0c][c0c], Asrc + (size_t)(bm + (p0 ? r0c : 0)) * 128 + kk + c0c, p0);
        cp16(&As[buf][r1c][c1c], Asrc + (size_t)(bm + (p1 ? r1c : 0)) * 128 + kk + c1c, p1);
        cp16(&Bs[buf][r0c][c0c], Wp + (size_t)(bn + r0c) * K + k0 + c0c, true);
        cp16(&Bs[buf][r1c][c1c], Wp + (size_t)(bn + r1c) * K + k0 + c1c, true);
        asm volatile("cp.async.commit_group;\n");
    };

    load_stage(0, 0);
    if (KT > 1) load_stage(1, 32); else asm volatile("cp.async.commit_group;\n");
    for (int kt = 0; kt < KT; kt++) {
        asm volatile("cp.async.wait_group 1;\n");   // stage kt resident
        __syncthreads();
        if (kt + 2 < KT) load_stage((kt + 2) % 3, (kt + 2) << 5);
        else asm volatile("cp.async.commit_group;\n");   // keep group count invariant
        const int buf = kt % 3;
        #pragma unroll
        for (int ks = 0; ks < 32; ks += 16) {
            unsigned a[2][4], b[8][2];
            #pragma unroll
            for (int mt = 0; mt < 2; mt++) {
                int rr = warp_m + mt * 16 + g;
                a[mt][0] = *(const unsigned*)&As[buf][rr][ks + 2 * q];
                a[mt][1] = *(const unsigned*)&As[buf][rr + 8][ks + 2 * q];
                a[mt][2] = *(const unsigned*)&As[buf][rr][ks + 2 * q + 8];
                a[mt][3] = *(const unsigned*)&As[buf][rr + 8][ks + 2 * q + 8];
            }
            #pragma unroll
            for (int nt = 0; nt < 8; nt++) {
                int c = warp_n + nt * 8 + g;
                b[nt][0] = *(const unsigned*)&Bs[buf][c][ks + 2 * q];
                b[nt][1] = *(const unsigned*)&Bs[buf][c][ks + 2 * q + 8];
            }
            #pragma unroll
            for (int mt = 0; mt < 2; mt++)
                #pragma unroll
                for (int nt = 0; nt < 8; nt++) {
                    float* cr = acc[mt][nt];
                    asm volatile(
                        "mma.sync.aligned.m16n8k16.row.col.f32.f16.f16.f32 "
                        "{%0,%1,%2,%3}, {%4,%5,%6,%7}, {%8,%9}, {%0,%1,%2,%3};\n"
                        : "+f"(cr[0]), "+f"(cr[1]), "+f"(cr[2]), "+f"(cr[3])
                        : "r"(a[mt][0]), "r"(a[mt][1]), "r"(a[mt][2]), "r"(a[mt][3]),
                          "r"(b[nt][0]), "r"(b[nt][1]));
                }
        }
    }
    // epilogue: bias + optional relu, fp16 output
    #pragma unroll
    for (int mt = 0; mt < 2; mt++) {
        int r0 = bm + warp_m + mt * 16 + g;
        #pragma unroll
        for (int nt = 0; nt < 8; nt++) {
            int c0 = bn + warp_n + nt * 8 + 2 * q;
            float bi0 = bias[c0], bi1 = bias[c0 + 1];
            if (r0 < M) {
                float v0 = acc[mt][nt][0] + bi0, v1 = acc[mt][nt][1] + bi1;
                if (RELU) { v0 = fmaxf(v0, 0.f); v1 = fmaxf(v1, 0.f); }
                *(__half2*)(C + (size_t)r0 * ldc + c0) = __floats2half2_rn(v0, v1);
            }
            if (r0 + 8 < M) {
                float v2 = acc[mt][nt][2] + bi0, v3 = acc[mt][nt][3] + bi1;
                if (RELU) { v2 = fmaxf(v2, 0.f); v3 = fmaxf(v3, 0.f); }
                *(__half2*)(C + (size_t)(r0 + 8) * ldc + c0) = __floats2half2_rn(v2, v3);
            }
        }
    }
}

// ---------------- per-edge prediction: warp handles EPW edges, W4 in regs ----------------
__global__ void k_edge(const float* __restrict__ W4, const float* __restrict__ b4,
                       float* __restrict__ out) {
    int tid = threadIdx.x, lane = tid & 31;
    int warp = (blockIdx.x * blockDim.x + tid) >> 5;
    float4 w0 = ((const float4*)W4)[lane * 2];
    float4 w1 = ((const float4*)W4)[lane * 2 + 1];
    float bb = b4[0];
    const __half2 hz = __floats2half2_rn(0.f, 0.f);
    int base = warp * EPW;
    #pragma unroll
    for (int i = 0; i < EPW; i++) {
        int p = base + i;
        if (p >= EE) return;
        int2 v = g_e2[p];
        int s = v.x & 0xffff;
        int d = (int)(((unsigned)v.x) >> 16);
        const uint4* Ar = (const uint4*)(g_ABh + (size_t)s * 512);
        const uint4* Br = (const uint4*)(g_ABh + (size_t)d * 512 + 256);
        uint4 a = Ar[lane];
        uint4 b = Br[lane];
        __half2 t0 = __hmax2(__hadd2(*(__half2*)&a.x, *(__half2*)&b.x), hz);
        __half2 t1 = __hmax2(__hadd2(*(__half2*)&a.y, *(__half2*)&b.y), hz);
        __half2 t2 = __hmax2(__hadd2(*(__half2*)&a.z, *(__half2*)&b.z), hz);
        __half2 t3 = __hmax2(__hadd2(*(__half2*)&a.w, *(__half2*)&b.w), hz);
        float2 f0 = __half22float2(t0), f1 = __half22float2(t1);
        float2 f2 = __half22float2(t2), f3 = __half22float2(t3);
        float acc = f0.x * w0.x + f0.y * w0.y + f1.x * w0.z + f1.y * w0.w +
                    f2.x * w1.x + f2.y * w1.y + f3.x * w1.z + f3.y * w1.w;
        #pragma unroll
        for (int o = 16; o; o >>= 1) acc += __shfl_down_sync(0xffffffffu, acc, o);
        if (lane == 0) out[v.y] = acc + bb;
    }
}

// ---------------- launch ----------------
extern "C" void kernel_launch(void* const* d_in, const int* in_sizes, int n_in,
                              void* d_out, int out_size) {
    const float* x   = (const float*)d_in[0];
    const int*   ei  = (const int*)d_in[1];   // dtype sniffed at runtime (int32 vs int64)
    const float* W1l = (const float*)d_in[2];
    const float* b1l = (const float*)d_in[3];
    const float* W1r = (const float*)d_in[4];
    const float* W2l = (const float*)d_in[5];
    const float* b2l = (const float*)d_in[6];
    const float* W2r = (const float*)d_in[7];
    const float* W3  = (const float*)d_in[8];
    const float* b3  = (const float*)d_in[9];
    const float* W4  = (const float*)d_in[10];
    const float* b4  = (const float*)d_in[11];
    float* out = (float*)d_out;

    __half *p_xh, *p_aggh, *p_h1h, *p_h2h, *p_ABh, *p_Wh;
    float  *p_bias;
    cudaGetSymbolAddress((void**)&p_xh,   g_xh);
    cudaGetSymbolAddress((void**)&p_aggh, g_aggh);
    cudaGetSymbolAddress((void**)&p_h1h,  g_h1h);
    cudaGetSymbolAddress((void**)&p_h2h,  g_h2h);
    cudaGetSymbolAddress((void**)&p_ABh,  g_ABh);
    cudaGetSymbolAddress((void**)&p_Wh,   g_WhA);
    cudaGetSymbolAddress((void**)&p_bias, g_biasA);

    const int TB = 256;
    // fused prologue: init + detect + pack all weights + x->fp16
    k_prolog<<<P4, TB>>>(ei, x, W1l, W1r, b1l, W2l, W2r, b2l, W3, b3);
    // CSR build: count(+decode+rank stash) -> one-shot base assignment -> atomic-free fill
    k_count<<<(EE + TB - 1) / TB, TB>>>(ei);
    k_ptr<<<NBLK, SCAN_B>>>();
    k_fill<<<(EE + TB - 1) / TB, TB>>>();

    const int aggGrid = (NN * 32 + TB - 1) / TB;
    const int mTiles  = (NN + 127) / 128;   // 391

    // SAGE layer 1: h1 = relu([mean_agg(x)|x] @ [W1l;W1r] + b1l) — root half read in-place
    k_agg<<<aggGrid, TB>>>(p_xh);
    gemm_h<true><<<dim3(1, mTiles), 256>>>(p_aggh, p_xh, NN, 256, p_Wh, p_bias, p_h1h, 128);

    // SAGE layer 2
    k_agg<<<aggGrid, TB>>>(p_h1h);
    gemm_h<true><<<dim3(1, mTiles), 256>>>(p_aggh, p_h1h, NN, 256, p_Wh + 512 * 128, p_bias + 512, p_h2h, 128);

    // Edge-MLP factorization: ABh[:,0:256] = h2@W3_top + b3, ABh[:,256:512] = h2@W3_bot
    gemm_h<false><<<dim3(4, mTiles), 256>>>(p_h2h, p_h2h, NN, 128, p_Wh + 2 * 512 * 128, p_bias + 2 * 512, p_ABh, 512);

    // Per-edge: dot(relu(A[src]+B[dst]), W4) + b4 (dst-grouped CSR order, EPW edges/warp)
    const int edgeWarps = (EE + EPW - 1) / EPW;
    k_edge<<<(edgeWarps * 32 + TB - 1) / TB, TB>>>(W4, b4, out);
}